// round 3
// baseline (speedup 1.0000x reference)
#include <cuda_runtime.h>

#define DIM     512
#define D_INNER 1024
#define DT_RANK 32
#define D_STATE 16
#define B_SZ    4
#define N_TOK   4097

// block-role layout (one kernel, 256 threads/block)
#define S0_BASE 0
#define S0_BLK  64
#define S1_BASE 64
#define S1_BLK  128
#define S2_BASE 192
#define S2_BLK  4
#define S3_BASE 196
#define S3_BLK  64
#define S4_BASE 260
#define S4_BLK  64
#define CP_BASE 324
#define CP_BLK  564
#define GRID_SZ (CP_BASE + CP_BLK)

// ---------------- scratch + sync state (device globals) ----------------
__device__ __align__(16) float g_q    [B_SZ * DIM];
__device__ __align__(16) float g_xs   [B_SZ * D_INNER];
__device__ __align__(16) float g_sz   [B_SZ * D_INNER];
__device__ __align__(16) float g_y    [B_SZ * D_INNER];
__device__ __align__(16) float g_mixed[B_SZ * DIM];
__device__ int gc0, gc1, gc2, gc3, gc4;   // zero-init; reset at end each launch

// ---------------- helpers ----------------
__device__ __forceinline__ float siluf(float x) { return x / (1.0f + __expf(-x)); }
__device__ __forceinline__ float softplusf(float x) {
    return (x > 20.0f) ? x : log1pf(__expf(x));
}
__device__ __forceinline__ void pf_l2(const float* p) {
    asm volatile("prefetch.global.L2 [%0];" :: "l"(p));
}
__device__ __forceinline__ void wait_cnt(int* c, int target) {
    if (threadIdx.x == 0) {
        while (*(volatile int*)c < target) __nanosleep(64);
        __threadfence();
    }
    __syncthreads();
}
__device__ __forceinline__ void signal_cnt(int* c) {
    __syncthreads();
    if (threadIdx.x == 0) { __threadfence(); atomicAdd(c, 1); }
}

// Warp-collective dot of two length-(N4*4) float vectors (float4 reads).
template <int N4>
__device__ __forceinline__ float warp_dot(const float4* __restrict__ v4,
                                          const float4* __restrict__ w4) {
    int lane = threadIdx.x & 31;
    float s = 0.0f;
#pragma unroll
    for (int i = 0; i < N4 / 32; i++) {
        float4 a = v4[lane + i * 32];
        float4 b = w4[lane + i * 32];
        s += a.x * b.x + a.y * b.y + a.z * b.z + a.w * b.w;
    }
#pragma unroll
    for (int off = 16; off; off >>= 1)
        s += __shfl_xor_sync(0xffffffffu, s, off);
    return s;
}

// ---------------- the one kernel ----------------
__global__ void __launch_bounds__(256, 6)
k_fused(const float* __restrict__ x,
        const float* __restrict__ q_w,
        const float* __restrict__ in_proj_w,
        const float* __restrict__ conv_w,
        const float* __restrict__ conv_b,
        const float* __restrict__ x_proj_w,
        const float* __restrict__ dt_w,
        const float* __restrict__ dt_b,
        const float* __restrict__ Dv,
        const float* __restrict__ out_proj_w,
        const float* __restrict__ proj_w,
        const float* __restrict__ proj_b,
        float* __restrict__ out) {
    const int t = threadIdx.x;
    const int lane = t & 31;
    const int wi = t >> 5;
    const unsigned bx = blockIdx.x;

    // ================= COPY blocks (bulk patch passthrough) =================
    if (bx >= CP_BASE) {
        const float4* x4 = (const float4*)x;
        float4* o4 = (float4*)out;
        const int pbg = (4096 * DIM / 4) / 4;      // 131072 groups-of-4 per batch
        const int totalg = B_SZ * pbg;             // 524288
        int tid = (bx - CP_BASE) * 256 + t;
        for (int g = tid; g < totalg; g += CP_BLK * 256) {
            int b   = g / pbg;
            int off = (g - b * pbg) * 4;
            int idx = b * (N_TOK * DIM / 4) + (DIM / 4) + off;  // skip cls token
            float4 v0 = x4[idx], v1 = x4[idx + 1], v2 = x4[idx + 2], v3 = x4[idx + 3];
            o4[idx] = v0; o4[idx + 1] = v1; o4[idx + 2] = v2; o4[idx + 3] = v3;
        }
        return;
    }

    // ================= S0: q = cls @ q_w.T (no wait) =================
    if (bx < S1_BASE) {
        int sb = bx - S0_BASE;
        int r0 = (sb * 32) % DIM;                  // 32 rows per block
#pragma unroll
        for (int k = 0; k < 2; k++) pf_l2(q_w + (size_t)r0 * DIM + (t * 2 + k) * 32);
        int gw = sb * 8 + wi;                      // 512 warps, 4 outputs each
#pragma unroll
        for (int j = 0; j < 4; j++) {
            int o = gw * 4 + j;
            int b = o / DIM, r = o % DIM;
            float s = warp_dot<DIM / 4>((const float4*)(x + (size_t)b * N_TOK * DIM),
                                        (const float4*)(q_w + (size_t)r * DIM));
            if (lane == 0) g_q[b * DIM + r] = s;
        }
        signal_cnt(&gc0);
        return;
    }

    // ================= S1: xz = q @ in_proj_w.T ; conv-tap + silu =================
    if (bx < S2_BASE) {
        int sb = bx - S1_BASE;
        int j0 = (sb * 64) % (2 * D_INNER);        // 64 rows per block
#pragma unroll
        for (int k = 0; k < 4; k++) pf_l2(in_proj_w + (size_t)j0 * DIM + (t * 4 + k) * 32);
        wait_cnt(&gc0, S0_BLK);
        int gw = sb * 8 + wi;                      // 1024 warps, 8 outputs each
#pragma unroll
        for (int jj = 0; jj < 8; jj++) {
            int o = gw * 8 + jj;
            int b = o / (2 * D_INNER), j = o % (2 * D_INNER);
            float s = warp_dot<DIM / 4>((const float4*)(g_q + b * DIM),
                                        (const float4*)(in_proj_w + (size_t)j * DIM));
            if (lane == 0) {
                if (j < D_INNER) {
                    // causal conv at t=0: only last tap contributes
                    float v = s * conv_w[j * 4 + 3] + conv_b[j];
                    g_xs[b * D_INNER + j] = siluf(v);
                } else {
                    g_sz[b * D_INNER + (j - D_INNER)] = siluf(s);
                }
            }
        }
        signal_cnt(&gc1);
        return;
    }

    // ================= S2: x_dbl + delta + first-step scan + gate =================
    if (bx < S3_BASE) {
        __shared__ __align__(16) float s_xs[D_INNER];
        __shared__ float s_db[DT_RANK + 2 * D_STATE];   // 64
        __shared__ float s_dtv[D_INNER];
        int b = bx - S2_BASE;
        // prefetch full x_proj_w (2048 lines) + dt_w (1024 lines); L2-dedup across 4 blocks
#pragma unroll
        for (int k = 0; k < 8; k++) pf_l2(x_proj_w + ((size_t)t * 8 + k) * 32);
#pragma unroll
        for (int k = 0; k < 4; k++) pf_l2(dt_w + ((size_t)t * 4 + k) * 32);
        wait_cnt(&gc1, S1_BLK);

        ((float4*)s_xs)[t] = ((const float4*)(g_xs + b * D_INNER))[t];
        __syncthreads();

        // 64 rows of x_proj: 8 warps x 8 rows
#pragma unroll
        for (int rr = 0; rr < 8; rr++) {
            int r = wi * 8 + rr;
            float s = warp_dot<D_INNER / 4>((const float4*)s_xs,
                                            (const float4*)(x_proj_w + (size_t)r * D_INNER));
            if (lane == 0) s_db[r] = s;
        }
        __syncthreads();

        // delta pre-act: 1024 rows, warp wi handles rows [wi*128, wi*128+128)
        float coef = s_db[lane];   // dt coefficient k = lane (DT_RANK == 32)
        for (int rr = 0; rr < 128; rr++) {
            int r = wi * 128 + rr;
            float v = dt_w[r * DT_RANK + lane] * coef;
#pragma unroll
            for (int off = 16; off; off >>= 1)
                v += __shfl_xor_sync(0xffffffffu, v, off);
            if (lane == 0) s_dtv[r] = v;
        }
        __syncthreads();

        float bc = 0.0f;
#pragma unroll
        for (int n = 0; n < D_STATE; n++)
            bc += s_db[DT_RANK + n] * s_db[DT_RANK + D_STATE + n];

#pragma unroll
        for (int p = 0; p < 4; p++) {
            int r = t + p * 256;
            float delta = softplusf(s_dtv[r] + dt_b[r]);
            float u = s_xs[r];
            // h0 = 0 => y = delta*u*(B.C) + u*D, gated by silu(z)
            g_y[b * D_INNER + r] = (delta * u * bc + u * Dv[r]) * g_sz[b * D_INNER + r];
        }
        signal_cnt(&gc2);
        return;
    }

    // ================= S3: mixed = y @ out_proj_w.T =================
    if (bx < S4_BASE) {
        int sb = bx - S3_BASE;
        int r0 = (sb * 32) % DIM;
#pragma unroll
        for (int k = 0; k < 4; k++) pf_l2(out_proj_w + (size_t)r0 * D_INNER + (t * 4 + k) * 32);
        wait_cnt(&gc2, S2_BLK);
        int gw = sb * 8 + wi;
#pragma unroll
        for (int j = 0; j < 4; j++) {
            int o = gw * 4 + j;
            int b = o / DIM, r = o % DIM;
            float s = warp_dot<D_INNER / 4>((const float4*)(g_y + b * D_INNER),
                                            (const float4*)(out_proj_w + (size_t)r * D_INNER));
            if (lane == 0) g_mixed[b * DIM + r] = s;
        }
        signal_cnt(&gc3);
        return;
    }

    // ================= S4: upd_cls = mixed @ proj_w.T + proj_b -> out[:,0,:] =====
    {
        int sb = bx - S4_BASE;
        int r0 = (sb * 32) % DIM;
#pragma unroll
        for (int k = 0; k < 2; k++) pf_l2(proj_w + (size_t)r0 * DIM + (t * 2 + k) * 32);
        wait_cnt(&gc3, S3_BLK);
        int gw = sb * 8 + wi;
#pragma unroll
        for (int j = 0; j < 4; j++) {
            int o = gw * 4 + j;
            int b = o / DIM, r = o % DIM;
            float s = warp_dot<DIM / 4>((const float4*)(g_mixed + b * DIM),
                                        (const float4*)(proj_w + (size_t)r * DIM));
            if (lane == 0)
                out[(size_t)b * N_TOK * DIM + r] = s + proj_b[r];
        }
        __syncthreads();
        if (t == 0) {
            __threadfence();
            int done = atomicAdd(&gc4, 1);
            if (done == S4_BLK - 1) {   // last block: reset for next graph replay
                gc0 = 0; gc1 = 0; gc2 = 0; gc3 = 0; gc4 = 0;
            }
        }
        return;
    }
}

// ---------------- launch ----------------
extern "C" void kernel_launch(void* const* d_in, const int* in_sizes, int n_in,
                              void* d_out, int out_size) {
    const float* x         = (const float*)d_in[0];
    const float* q_w       = (const float*)d_in[1];
    const float* in_proj_w = (const float*)d_in[2];
    const float* conv_w    = (const float*)d_in[3];
    const float* conv_b    = (const float*)d_in[4];
    const float* x_proj_w  = (const float*)d_in[5];
    const float* dt_w      = (const float*)d_in[6];
    const float* dt_b      = (const float*)d_in[7];
    // d_in[8] = A_log (unused: h0 = 0 at the single contributing scan step)
    const float* Dv        = (const float*)d_in[9];
    const float* out_proj_w= (const float*)d_in[10];
    const float* proj_w    = (const float*)d_in[11];
    const float* proj_b    = (const float*)d_in[12];
    float* out = (float*)d_out;

    k_fused<<<GRID_SZ, 256>>>(x, q_w, in_proj_w, conv_w, conv_b, x_proj_w,
                              dt_w, dt_b, Dv, out_proj_w, proj_w, proj_b, out);
}